// round 16
// baseline (speedup 1.0000x reference)
#include <cuda_runtime.h>
#include <cuda_fp16.h>
#include <cstdint>
#include <cstddef>

#define EPSV 1e-5f

// problem dims (fixed)
#define NB 2
#define NC 64
#define NT 2048
#define NF 64
#define NH 4
#define NHC 4
#define NVC 16
#define DQK 256   // NHC*NF
#define DV  1024  // NVC*NF
#define NHB 8     // NH*NB
#define NTF 131072  // NT*NF per (b,c)

// ---------------- scratch (device globals; no allocations allowed) ----------
__device__ __half g_Q[(size_t)NHB * NT * DQK];   // 8 MB
__device__ __half g_K[(size_t)NHB * NT * DQK];   // 8 MB
__device__ __half g_V[(size_t)NHB * NT * DV];    // 32 MB
__device__ __half g_Vt[(size_t)NHB * DV * NT];   // 32 MB  V^T per z: [dv][t]
__device__ __half g_E[(size_t)NHB * NT * NT];    // 64 MB  exp(alpha*S)
__device__ float  g_O[(size_t)NHB * NT * DV];    // 64 MB

// ---------------- helpers ----------------------------------------------------
__device__ __forceinline__ uint32_t smem_u32(const void* p) {
    uint32_t a;
    asm("{ .reg .u64 t; cvta.to.shared.u64 t, %1; cvt.u32.u64 %0, t; }" : "=r"(a) : "l"(p));
    return a;
}
__device__ __forceinline__ void cp_async16(uint32_t dst, const void* src) {
    asm volatile("cp.async.cg.shared.global [%0], [%1], 16;" :: "r"(dst), "l"(src) : "memory");
}
__device__ __forceinline__ void cp_commit() { asm volatile("cp.async.commit_group;" ::: "memory"); }
template <int N> __device__ __forceinline__ void cp_wait() {
    asm volatile("cp.async.wait_group %0;" :: "n"(N) : "memory");
}
__device__ __forceinline__ void mma_f16(float* c, const uint32_t* a, const uint32_t* b) {
    asm volatile(
        "mma.sync.aligned.m16n8k16.row.col.f32.f16.f16.f32 "
        "{%0,%1,%2,%3}, {%4,%5,%6,%7}, {%8,%9}, {%0,%1,%2,%3};"
        : "+f"(c[0]), "+f"(c[1]), "+f"(c[2]), "+f"(c[3])
        : "r"(a[0]), "r"(a[1]), "r"(a[2]), "r"(a[3]), "r"(b[0]), "r"(b[1]));
}
__device__ __forceinline__ void ldmx4(uint32_t& r0, uint32_t& r1, uint32_t& r2, uint32_t& r3,
                                      uint32_t addr) {
    asm volatile("ldmatrix.sync.aligned.m8n8.x4.shared.b16 {%0,%1,%2,%3}, [%4];"
        : "=r"(r0), "=r"(r1), "=r"(r2), "=r"(r3) : "r"(addr));
}
__device__ __forceinline__ float2 h2f2(uint32_t u) {
    return __half22float2(*reinterpret_cast<__half2*>(&u));
}

// common GEMM tile geometry: 128x128 tile, 2 CTAs/SM
#define BM 128
#define BN 128
#define BKH 64                       // k halfs per stage
#define SH 72                        // smem row stride in halfs (144 B)
#define A2_TILE_BYTES (BM * SH * 2)  // 18432
#define B2_TILE_BYTES (BN * SH * 2)  // 18432
#define STAGE_BYTES (A2_TILE_BYTES + B2_TILE_BYTES)  // 36864
#define NSTG 3
#define SMEM_GEMM (NSTG * STAGE_BYTES)               // 110592

#define ISSUE_F16(it, Kd) do {                                                  \
        int _st = (it) % NSTG;                                                  \
        uint32_t _as = smem_u32(smem) + _st * STAGE_BYTES;                      \
        uint32_t _bs = _as + A2_TILE_BYTES;                                     \
        const __half* _ga = A + (size_t)bm * (Kd) + (size_t)(it) * BKH;         \
        const __half* _gb = B + (size_t)bn * (Kd) + (size_t)(it) * BKH;         \
        _Pragma("unroll")                                                       \
        for (int j = 0; j < 4; j++) {                                           \
            int idx = tid + j * 256;                                            \
            int row = idx >> 3, c8 = idx & 7;                                   \
            cp_async16(_as + (uint32_t)(row * SH * 2 + c8 * 16),                \
                       _ga + (size_t)row * (Kd) + c8 * 8);                      \
        }                                                                       \
        _Pragma("unroll")                                                       \
        for (int j = 0; j < 4; j++) {                                           \
            int idx = tid + j * 256;                                            \
            int row = idx >> 3, c8 = idx & 7;                                   \
            cp_async16(_bs + (uint32_t)(row * SH * 2 + c8 * 16),                \
                       _gb + (size_t)row * (Kd) + c8 * 8);                      \
        }                                                                       \
        cp_commit();                                                            \
    } while (0)

// per-lane ldmatrix base offsets (bytes; stride SH halfs)
#define A_LDM_OFF(base_row) ((uint32_t)(((base_row) + (lane & 15)) * (SH * 2) + (lane >> 4) * 16))
#define B_LDM_OFF(base_row) ((uint32_t)(((base_row) + ((lane & 16) >> 1) + (lane & 7)) * (SH * 2) + ((lane >> 3) & 1) * 16))

// ldmatrix offset macros for qkv_tc (stride QSH halfs)
#define QSH 72
#define A_LDM_OFF_Q(base_row) ((uint32_t)(((base_row) + (lane & 15)) * (QSH * 2) + (lane >> 4) * 16))
#define B_LDM_OFF_Q(base_row) ((uint32_t)(((base_row) + ((lane & 16) >> 1) + (lane & 7)) * (QSH * 2) + ((lane >> 3) & 1) * 16))

// ================= GEMM 1 (fp16): E = fp16(exp(alpha * Q K^T)) ===============
__global__ __launch_bounds__(256, 2) void gemm_qk_exp(
    const __half* __restrict__ A, const __half* __restrict__ B, __half* __restrict__ C,
    float alpha, size_t sA, size_t sB, size_t sC)
{
    extern __shared__ char smem[];
    const int tid = threadIdx.x;
    const int wid = tid >> 5;
    const int lane = tid & 31;
    const int g = lane >> 2;
    const int tc = lane & 3;

    A += (size_t)blockIdx.z * sA;
    B += (size_t)blockIdx.z * sB;
    C += (size_t)blockIdx.z * sC;
    const int bm = blockIdx.y * BM;
    const int bn = blockIdx.x * BN;
    const int wm = (wid & 1) * 64;
    const int wn = (wid >> 1) * 32;

    uint32_t aOff[4], bOff[2];
#pragma unroll
    for (int mt = 0; mt < 4; mt++) aOff[mt] = A_LDM_OFF(wm + mt * 16);
#pragma unroll
    for (int q = 0; q < 2; q++) bOff[q] = B_LDM_OFF(wn + q * 16) + A2_TILE_BYTES;

    float acc[4][4][4];
#pragma unroll
    for (int mt = 0; mt < 4; mt++)
#pragma unroll
        for (int nt = 0; nt < 4; nt++)
#pragma unroll
            for (int i = 0; i < 4; i++) acc[mt][nt][i] = 0.f;

    const int nk = DQK / BKH;   // 4

    ISSUE_F16(0, DQK);
    ISSUE_F16(1, DQK);

    for (int it = 0; it < nk; it++) {
        if (it < nk - 1) cp_wait<1>(); else cp_wait<0>();
        __syncthreads();
        if (it + 2 < nk) ISSUE_F16(it + 2, DQK);

        uint32_t stg = smem_u32(smem) + (it % NSTG) * STAGE_BYTES;

#pragma unroll
        for (int ks = 0; ks < 4; ks++) {
            uint32_t koff = stg + ks * 32;
            uint32_t a[4][4], b[4][2];
#pragma unroll
            for (int mt = 0; mt < 4; mt++)
                ldmx4(a[mt][0], a[mt][1], a[mt][2], a[mt][3], koff + aOff[mt]);
#pragma unroll
            for (int q = 0; q < 2; q++)
                ldmx4(b[2 * q][0], b[2 * q][1], b[2 * q + 1][0], b[2 * q + 1][1],
                      koff + bOff[q]);
#pragma unroll
            for (int mt = 0; mt < 4; mt++)
#pragma unroll
                for (int nt = 0; nt < 4; nt++)
                    mma_f16(acc[mt][nt], a[mt], b[nt]);
        }
    }

    // epilogue: E = fp16(exp(alpha * S))
#pragma unroll
    for (int mt = 0; mt < 4; mt++) {
#pragma unroll
        for (int nt = 0; nt < 4; nt++) {
            int row = bm + wm + mt * 16 + g;
            int col = bn + wn + nt * 8 + 2 * tc;
            __half2 e0 = __float22half2_rn(
                make_float2(__expf(acc[mt][nt][0] * alpha), __expf(acc[mt][nt][1] * alpha)));
            __half2 e1 = __float22half2_rn(
                make_float2(__expf(acc[mt][nt][2] * alpha), __expf(acc[mt][nt][3] * alpha)));
            *(uint32_t*)&C[(size_t)row * NT + col]       = *(uint32_t*)&e0;
            *(uint32_t*)&C[(size_t)(row + 8) * NT + col] = *(uint32_t*)&e1;
        }
    }
}

// ================= GEMM 2 (fp16): O = (E V) / rowsum(E) ======================
// z index = blockIdx.z * NB + zoff  (b-sliced for stream overlap)
__global__ __launch_bounds__(256, 2) void gemm_pv_norm(
    const __half* __restrict__ A, const __half* __restrict__ B,
    float* __restrict__ C, size_t sA, size_t sB, size_t sC, int zoff)
{
    extern __shared__ char smem[];
    __shared__ float rowinv[BM];
    const int tid = threadIdx.x;
    const int wid = tid >> 5;
    const int lane = tid & 31;
    const int g = lane >> 2;
    const int tc = lane & 3;

    const int zi = blockIdx.z * NB + zoff;
    A += (size_t)zi * sA;
    B += (size_t)zi * sB;
    C += (size_t)zi * sC;
    const int bm = blockIdx.y * BM;
    const int bn = blockIdx.x * BN;
    const int wm = (wid & 1) * 64;
    const int wn = (wid >> 1) * 32;

    uint32_t aOff[4], bOff[2];
#pragma unroll
    for (int mt = 0; mt < 4; mt++) aOff[mt] = A_LDM_OFF(wm + mt * 16);
#pragma unroll
    for (int q = 0; q < 2; q++) bOff[q] = B_LDM_OFF(wn + q * 16) + A2_TILE_BYTES;

    float acc[4][4][4];
#pragma unroll
    for (int mt = 0; mt < 4; mt++)
#pragma unroll
        for (int nt = 0; nt < 4; nt++)
#pragma unroll
            for (int i = 0; i < 4; i++) acc[mt][nt][i] = 0.f;

    float rs[4][2];
#pragma unroll
    for (int mt = 0; mt < 4; mt++) { rs[mt][0] = 0.f; rs[mt][1] = 0.f; }

    const int nk = NT / BKH;   // 32

    ISSUE_F16(0, NT);
    ISSUE_F16(1, NT);

    for (int it = 0; it < nk; it++) {
        if (it < nk - 1) cp_wait<1>(); else cp_wait<0>();
        __syncthreads();
        if (it + 2 < nk) ISSUE_F16(it + 2, NT);

        uint32_t stg = smem_u32(smem) + (it % NSTG) * STAGE_BYTES;

#pragma unroll
        for (int ks = 0; ks < 4; ks++) {
            uint32_t koff = stg + ks * 32;
            uint32_t a[4][4], b[4][2];
#pragma unroll
            for (int mt = 0; mt < 4; mt++)
                ldmx4(a[mt][0], a[mt][1], a[mt][2], a[mt][3], koff + aOff[mt]);
            if (wid < 2) {   // wn==0 warps: exact row sums of E
#pragma unroll
                for (int mt = 0; mt < 4; mt++) {
                    float2 f0 = h2f2(a[mt][0]), f2 = h2f2(a[mt][2]);
                    float2 f1 = h2f2(a[mt][1]), f3 = h2f2(a[mt][3]);
                    rs[mt][0] += (f0.x + f0.y) + (f2.x + f2.y);
                    rs[mt][1] += (f1.x + f1.y) + (f3.x + f3.y);
                }
            }
#pragma unroll
            for (int q = 0; q < 2; q++)
                ldmx4(b[2 * q][0], b[2 * q][1], b[2 * q + 1][0], b[2 * q + 1][1],
                      koff + bOff[q]);
#pragma unroll
            for (int mt = 0; mt < 4; mt++)
#pragma unroll
                for (int nt = 0; nt < 4; nt++)
                    mma_f16(acc[mt][nt], a[mt], b[nt]);
        }
    }

    if (wid < 2) {
#pragma unroll
        for (int mt = 0; mt < 4; mt++) {
#pragma unroll
            for (int h2 = 0; h2 < 2; h2++) {
                float s = rs[mt][h2];
                s += __shfl_xor_sync(0xffffffffu, s, 1);
                s += __shfl_xor_sync(0xffffffffu, s, 2);
                if (tc == 0) rowinv[wm + mt * 16 + g + h2 * 8] = 1.f / s;
            }
        }
    }
    __syncthreads();

#pragma unroll
    for (int mt = 0; mt < 4; mt++) {
        float inv0 = rowinv[wm + mt * 16 + g];
        float inv1 = rowinv[wm + mt * 16 + g + 8];
#pragma unroll
        for (int nt = 0; nt < 4; nt++) {
            int row = bm + wm + mt * 16 + g;
            int col = bn + wn + nt * 8 + 2 * tc;
            float2 v0 = make_float2(acc[mt][nt][0] * inv0, acc[mt][nt][1] * inv0);
            float2 v1 = make_float2(acc[mt][nt][2] * inv1, acc[mt][nt][3] * inv1);
            *(float2*)&C[(size_t)row * DV + col] = v0;
            *(float2*)&C[(size_t)(row + 8) * DV + col] = v1;
        }
    }
}

// ---------------- kernel 1: tensor-core QKV projection + PReLU + LN ----------
#define SM_W 0
#define SM_X 13824
#define SM_OUT 50688
#define SMEM_QKV (SM_OUT + 128 * 97 * 4)    // 100352 B

__global__ __launch_bounds__(256, 1) void qkv_tc(
    const float* __restrict__ x,
    const float* __restrict__ Wq, const float* __restrict__ bq, const float* __restrict__ aq,
    const float* __restrict__ gq, const float* __restrict__ betaq,
    const float* __restrict__ Wk, const float* __restrict__ bk, const float* __restrict__ ak,
    const float* __restrict__ gk, const float* __restrict__ betak,
    const float* __restrict__ Wv, const float* __restrict__ bv, const float* __restrict__ av,
    const float* __restrict__ gv, const float* __restrict__ betav)
{
    extern __shared__ char smem[];
    __half* sW = (__half*)(smem + SM_W);
    __half* sX = (__half*)(smem + SM_X);
    float* sOut = (float*)(smem + SM_OUT);

    const int tid = threadIdx.x;
    const int wid = tid >> 5;
    const int lane = tid & 31;
    const int g = lane >> 2;
    const int tc = lane & 3;
    const int b = blockIdx.y;
    const int nbase = blockIdx.x * 256;

    for (int i = tid; i < 96 * 64; i += 256) {
        int row = i >> 6, c = i & 63;
        float w;
        if (row < 16)      w = Wq[row * NC + c];
        else if (row < 32) w = Wk[(row - 16) * NC + c];
        else               w = Wv[(row - 32) * NC + c];
        sW[row * QSH + c] = __float2half_rn(w);
    }
    {
        const float* xpf = x + (size_t)b * NC * NTF + nbase;
        for (int i = tid; i < 64 * 128; i += 256) {
            int r = i >> 7;
            int u = i & 127;
            float2 v = *(const float2*)(xpf + (size_t)r * NTF + 2 * u);
            sX[(2 * u) * QSH + r]     = __float2half_rn(v.x);
            sX[(2 * u + 1) * QSH + r] = __float2half_rn(v.y);
        }
    }
    __syncthreads();

    const int wm = (wid & 1) * 48;
    const int wn = (wid >> 1) * 64;
    uint32_t sWb = smem_u32(sW);
    uint32_t sXb = smem_u32(sX);

    uint32_t a[3][4][4];
#pragma unroll
    for (int mt = 0; mt < 3; mt++) {
        uint32_t off = sWb + A_LDM_OFF_Q(wm + mt * 16);
#pragma unroll
        for (int ks = 0; ks < 4; ks++)
            ldmx4(a[mt][ks][0], a[mt][ks][1], a[mt][ks][2], a[mt][ks][3], off + ks * 32);
    }

    float acc[3][8][4];
#pragma unroll
    for (int mt = 0; mt < 3; mt++)
#pragma unroll
        for (int nt = 0; nt < 8; nt++)
#pragma unroll
            for (int i = 0; i < 4; i++) acc[mt][nt][i] = 0.f;

#pragma unroll
    for (int ks = 0; ks < 4; ks++) {
        uint32_t b2[8][2];
#pragma unroll
        for (int q = 0; q < 4; q++) {
            uint32_t off = sXb + B_LDM_OFF_Q(wn + q * 16) + ks * 32;
            ldmx4(b2[2 * q][0], b2[2 * q][1], b2[2 * q + 1][0], b2[2 * q + 1][1], off);
        }
#pragma unroll
        for (int mt = 0; mt < 3; mt++)
#pragma unroll
            for (int nt = 0; nt < 8; nt++)
                mma_f16(acc[mt][nt], a[mt][ks], b2[nt]);
    }

#pragma unroll 1
    for (int bt = 0; bt < 2; bt++) {
        __syncthreads();
        if ((wid >> 2) == bt) {
#pragma unroll
            for (int mt = 0; mt < 3; mt++)
#pragma unroll
                for (int nt = 0; nt < 8; nt++)
#pragma unroll
                    for (int i = 0; i < 4; i++) {
                        int row = wm + mt * 16 + g + 8 * (i >> 1);
                        int col = (wn - bt * 128) + nt * 8 + 2 * tc + (i & 1);
                        sOut[col * 97 + row] = acc[mt][nt][i];
                    }
        }
        __syncthreads();
        {
            const int c = tid & 127;
            const int hh = tid >> 7;
            const int n = nbase + bt * 128 + c;
            const int t = n >> 6;
            const int f = n & 63;
            const float* so = sOut + c * 97;

#pragma unroll
            for (int h2 = 0; h2 < 2; h2++) {
                const int h = hh * 2 + h2;
                {
                    float y[4]; float aph = aq[h]; float mu = 0.f;
#pragma unroll
                    for (int j = 0; j < 4; j++) {
                        float v = so[4 * h + j] + bq[4 * h + j];
                        v = (v >= 0.f) ? v : aph * v;
                        y[j] = v; mu += v;
                    }
                    mu *= 0.25f;
                    float var = 0.f;
#pragma unroll
                    for (int j = 0; j < 4; j++) { float d = y[j] - mu; var += d * d; }
                    float r = rsqrtf(var * 0.25f + EPSV);
#pragma unroll
                    for (int j = 0; j < 4; j++) {
                        float o = (y[j] - mu) * r * gq[4 * h + j] + betaq[4 * h + j];
                        g_Q[((size_t)(h * NB + b) * NT + t) * DQK + j * NF + f] = __float2half_rn(o);
                    }
                }
                {
                    float y[4]; float aph = ak[h]; float mu = 0.f;
#pragma unroll
                    for (int j = 0; j < 4; j++) {
                        float v = so[16 + 4 * h + j] + bk[4 * h + j];
                        v = (v >= 0.f) ? v : aph * v;
                        y[j] = v; mu += v;
                    }
                    mu *= 0.25f;
                    float var = 0.f;
#pragma unroll
                    for (int j = 0; j < 4; j++) { float d = y[j] - mu; var += d * d; }
                    float r = rsqrtf(var * 0.25f + EPSV);
#pragma unroll
                    for (int j = 0; j < 4; j++) {
                        float o = (y[j] - mu) * r * gk[4 * h + j] + betak[4 * h + j];
                        g_K[((size_t)(h * NB + b) * NT + t) * DQK + j * NF + f] = __float2half_rn(o);
                    }
                }
                {
                    float y[16]; float aph = av[h]; float mu = 0.f;
#pragma unroll
                    for (int j = 0; j < 16; j++) {
                        float v = so[32 + 16 * h + j] + bv[16 * h + j];
                        v = (v >= 0.f) ? v : aph * v;
                        y[j] = v; mu += v;
                    }
                    mu *= (1.f / 16.f);
                    float var = 0.f;
#pragma unroll
                    for (int j = 0; j < 16; j++) { float d = y[j] - mu; var += d * d; }
                    float r = rsqrtf(var * (1.f / 16.f) + EPSV);
#pragma unroll
                    for (int j = 0; j < 16; j++) {
                        float o = (y[j] - mu) * r * gv[16 * h + j] + betav[16 * h + j];
                        g_V[((size_t)(h * NB + b) * NT + t) * DV + j * NF + f] = __float2half_rn(o);
                    }
                }
            }
        }
    }
}

// ---------------- transpose V (fp16): [t][dv] -> [dv][t] per z ----------------
__global__ __launch_bounds__(256) void transpose_v()
{
    __shared__ __half tile[32][33];
    int bt = blockIdx.x * 32, bd = blockIdx.y * 32;
    size_t base = (size_t)blockIdx.z * NT * DV;
    int tx = threadIdx.x, ty = threadIdx.y;
#pragma unroll
    for (int j = 0; j < 4; j++)
        tile[ty + j * 8][tx] = g_V[base + (size_t)(bt + ty + j * 8) * DV + bd + tx];
    __syncthreads();
#pragma unroll
    for (int j = 0; j < 4; j++)
        g_Vt[base + (size_t)(bd + ty + j * 8) * NT + bt + tx] = tile[tx][ty + j * 8];
}

// ---------------- out_kernel v4: projection + PReLU + LN + residual ----------
// per-b launch; block = 256 threads handles TWO t positions.
#define OK_SWT 0
#define OK_SOG 17408
#define OK_RED (OK_SOG + 2 * 17408)
#define SMEM_OUTK (OK_RED + 4096)         // 56320

__global__ __launch_bounds__(256, 2) void out_kernel(
    const float* __restrict__ x,
    const float* __restrict__ Wp, const float* __restrict__ bp, const float* __restrict__ ap,
    const float* __restrict__ gp, const float* __restrict__ betap,
    float* __restrict__ out, int b)
{
    extern __shared__ char smem[];
    float* sWt = (float*)(smem + OK_SWT);
    float* sOg = (float*)(smem + OK_SOG);
    float* sred = (float*)(smem + OK_RED);

    const int tid = threadIdx.x;
    const int t0 = blockIdx.x * 2;

    for (int i = tid; i < NC * NC; i += 256) {
        int o = i >> 6, c = i & 63;
        sWt[c * 68 + o] = Wp[i];
    }
#pragma unroll
    for (int tt = 0; tt < 2; tt++) {
#pragma unroll
        for (int h = 0; h < NH; h++) {
            const float4* src = (const float4*)&g_O[((size_t)(h * NB + b) * NT + t0 + tt) * DV];
            float4 val = src[tid];
            int vc = tid >> 4;
            int f0 = (tid & 15) * 4;
            *(float4*)&sOg[tt * (NC * 68) + (h * 16 + vc) * 68 + f0] = val;
        }
    }
    __syncthreads();

    const int j = tid >> 6;
    const int f = tid & 63;
    const int o0 = 16 * j;

    float acc0[16], acc1[16];
#pragma unroll
    for (int i = 0; i < 16; i++) { acc0[i] = 0.f; acc1[i] = 0.f; }

#pragma unroll 4
    for (int c = 0; c < NC; c++) {
        float oga = sOg[c * 68 + f];
        float ogb = sOg[NC * 68 + c * 68 + f];
        float4 w0 = *(const float4*)&sWt[c * 68 + o0];
        float4 w1 = *(const float4*)&sWt[c * 68 + o0 + 4];
        float4 w2 = *(const float4*)&sWt[c * 68 + o0 + 8];
        float4 w3 = *(const float4*)&sWt[c * 68 + o0 + 12];
        acc0[0] += w0.x * oga;  acc0[1] += w0.y * oga;  acc0[2] += w0.z * oga;  acc0[3] += w0.w * oga;
        acc0[4] += w1.x * oga;  acc0[5] += w1.y * oga;  acc0[6] += w1.z * oga;  acc0[7] += w1.w * oga;
        acc0[8] += w2.x * oga;  acc0[9] += w2.y * oga;  acc0[10] += w2.z * oga; acc0[11] += w2.w * oga;
        acc0[12] += w3.x * oga; acc0[13] += w3.y * oga; acc0[14] += w3.z * oga; acc0[15] += w3.w * oga;
        acc1[0] += w0.x * ogb;  acc1[1] += w0.y * ogb;  acc1[2] += w0.z * ogb;  acc1[3] += w0.w * ogb;
        acc1[4] += w1.x * ogb;  acc1[5] += w1.y * ogb;  acc1[6] += w1.z * ogb;  acc1[7] += w1.w * ogb;
        acc1[8] += w2.x * ogb;  acc1[9] += w2.y * ogb;  acc1[10] += w2.z * ogb; acc1[11] += w2.w * ogb;
        acc1[12] += w3.x * ogb; acc1[13] += w3.y * ogb; acc1[14] += w3.z * ogb; acc1[15] += w3.w * ogb;
    }

    float a = ap[0];
    {
        float s1 = 0.f, s2 = 0.f, u1 = 0.f, u2 = 0.f;
#pragma unroll
        for (int i = 0; i < 16; i++) {
            float y = acc0[i] + bp[o0 + i];
            y = (y >= 0.f) ? y : a * y;
            acc0[i] = y; s1 += y; s2 += y * y;
            float z = acc1[i] + bp[o0 + i];
            z = (z >= 0.f) ? z : a * z;
            acc1[i] = z; u1 += z; u2 += z * z;
        }
        sred[((0 * 2 + 0) * 4 + j) * 64 + f] = s1;
        sred[((1 * 2 + 0) * 4 + j) * 64 + f] = s2;
        sred[((0 * 2 + 1) * 4 + j) * 64 + f] = u1;
        sred[((1 * 2 + 1) * 4 + j) * 64 + f] = u2;
    }
    __syncthreads();

#pragma unroll
    for (int tt = 0; tt < 2; tt++) {
        float* base1 = sred + (0 * 2 + tt) * 4 * 64;
        float* base2 = sred + (1 * 2 + tt) * 4 * 64;
        float s1 = base1[0 * 64 + f] + base1[1 * 64 + f] + base1[2 * 64 + f] + base1[3 * 64 + f];
        float s2 = base2[0 * 64 + f] + base2[1 * 64 + f] + base2[2 * 64 + f] + base2[3 * 64 + f];
        float mu = s1 * (1.f / NC);
        float var = s2 * (1.f / NC) - mu * mu;
        float r = rsqrtf(var + EPSV);
        float* acc = tt ? acc1 : acc0;
#pragma unroll
        for (int i = 0; i < 16; i++) {
            int o = o0 + i;
            size_t idx = (((size_t)b * NC + o) * NT + t0 + tt) * NF + f;
            out[idx] = (acc[i] - mu) * r * gp[o] + betap[o] + x[idx];
        }
    }
}

// ---------------- launch ------------------------------------------------------
extern "C" void kernel_launch(void* const* d_in, const int* in_sizes, int n_in,
                              void* d_out, int out_size)
{
    const float* x     = (const float*)d_in[0];
    const float* Wq    = (const float*)d_in[1];
    const float* bq    = (const float*)d_in[2];
    const float* aq    = (const float*)d_in[3];
    const float* gq    = (const float*)d_in[4];
    const float* betaq = (const float*)d_in[5];
    const float* Wk    = (const float*)d_in[6];
    const float* bk    = (const float*)d_in[7];
    const float* ak    = (const float*)d_in[8];
    const float* gk    = (const float*)d_in[9];
    const float* betak = (const float*)d_in[10];
    const float* Wv    = (const float*)d_in[11];
    const float* bv    = (const float*)d_in[12];
    const float* av    = (const float*)d_in[13];
    const float* gv    = (const float*)d_in[14];
    const float* betav = (const float*)d_in[15];
    const float* Wp    = (const float*)d_in[16];
    const float* bp    = (const float*)d_in[17];
    const float* ap    = (const float*)d_in[18];
    const float* gp    = (const float*)d_in[19];
    const float* betap = (const float*)d_in[20];
    float* out = (float*)d_out;

    float* pO;
    __half *pQ, *pK, *pV, *pVt, *pE;
    cudaGetSymbolAddress((void**)&pQ, g_Q);
    cudaGetSymbolAddress((void**)&pK, g_K);
    cudaGetSymbolAddress((void**)&pV, g_V);
    cudaGetSymbolAddress((void**)&pVt, g_Vt);
    cudaGetSymbolAddress((void**)&pE, g_E);
    cudaGetSymbolAddress((void**)&pO, g_O);

    cudaFuncSetAttribute(gemm_qk_exp, cudaFuncAttributeMaxDynamicSharedMemorySize, SMEM_GEMM);
    cudaFuncSetAttribute(gemm_pv_norm, cudaFuncAttributeMaxDynamicSharedMemorySize, SMEM_GEMM);
    cudaFuncSetAttribute(qkv_tc, cudaFuncAttributeMaxDynamicSharedMemorySize, SMEM_QKV);
    cudaFuncSetAttribute(out_kernel, cudaFuncAttributeMaxDynamicSharedMemorySize, SMEM_OUTK);

    // streams/events created once on the (uncaptured) correctness call
    static cudaStream_t s1 = nullptr;
    static cudaEvent_t evQKV, evT, evPV0, evOut0;
    if (s1 == nullptr) {
        cudaStreamCreateWithFlags(&s1, cudaStreamNonBlocking);
        cudaEventCreateWithFlags(&evQKV, cudaEventDisableTiming);
        cudaEventCreateWithFlags(&evT, cudaEventDisableTiming);
        cudaEventCreateWithFlags(&evPV0, cudaEventDisableTiming);
        cudaEventCreateWithFlags(&evOut0, cudaEventDisableTiming);
    }

    // 1) QKV projection (stream 0)
    qkv_tc<<<dim3(NTF / 256, NB), 256, SMEM_QKV>>>(
        x, Wq, bq, aq, gq, betaq, Wk, bk, ak, gk, betak, Wv, bv, av, gv, betav);
    cudaEventRecord(evQKV, 0);

    // 2) V transpose on s1 (overlaps gemm_qk on stream 0)
    cudaStreamWaitEvent(s1, evQKV, 0);
    transpose_v<<<dim3(NT / 32, DV / 32, NHB), dim3(32, 8), 0, s1>>>();
    cudaEventRecord(evT, s1);

    // 3) E = exp(QK^T) on stream 0 (all z)
    gemm_qk_exp<<<dim3(NT / BN, NT / BM, NHB), 256, SMEM_GEMM>>>(
        pQ, pK, pE, 0.0625f,
        (size_t)NT * DQK, (size_t)NT * DQK, (size_t)NT * NT);

    // 4a) pv for b=0 (z = 0,2,4,6) on stream 0 (after transpose)
    cudaStreamWaitEvent(0, evT, 0);
    gemm_pv_norm<<<dim3(DV / BN, NT / BM, NH), 256, SMEM_GEMM>>>(
        pE, pVt, pO,
        (size_t)NT * NT, (size_t)DV * NT, (size_t)NT * DV, 0);
    cudaEventRecord(evPV0, 0);

    // 5a) out for b=0 on s1 (overlaps pv b=1)
    cudaStreamWaitEvent(s1, evPV0, 0);
    out_kernel<<<dim3(NT / 2), 256, SMEM_OUTK, s1>>>(
        x, Wp, bp, ap, gp, betap, out, 0);
    cudaEventRecord(evOut0, s1);

    // 4b) pv for b=1 (z = 1,3,5,7) on stream 0
    gemm_pv_norm<<<dim3(DV / BN, NT / BM, NH), 256, SMEM_GEMM>>>(
        pE, pVt, pO,
        (size_t)NT * NT, (size_t)DV * NT, (size_t)NT * DV, 1);

    // 5b) out for b=1 on stream 0; join s1 back first
    cudaStreamWaitEvent(0, evOut0, 0);
    out_kernel<<<dim3(NT / 2), 256, SMEM_OUTK>>>(
        x, Wp, bp, ap, gp, betap, out, 1);
}

// round 17
// speedup vs baseline: 1.0855x; 1.0855x over previous
#include <cuda_runtime.h>
#include <cuda_fp16.h>
#include <cstdint>
#include <cstddef>

#define EPSV 1e-5f

// problem dims (fixed)
#define NB 2
#define NC 64
#define NT 2048
#define NF 64
#define NH 4
#define NHC 4
#define NVC 16
#define DQK 256   // NHC*NF
#define DV  1024  // NVC*NF
#define NHB 8     // NH*NB
#define NTF 131072  // NT*NF per (b,c)

// ---------------- scratch (device globals; no allocations allowed) ----------
__device__ __half g_Q[(size_t)NHB * NT * DQK];   // 8 MB
__device__ __half g_K[(size_t)NHB * NT * DQK];   // 8 MB
__device__ __half g_V[(size_t)NHB * NT * DV];    // 32 MB
__device__ __half g_Vt[(size_t)NHB * DV * NT];   // 32 MB  V^T per z: [dv][t]
__device__ __half g_E[(size_t)NHB * NT * NT];    // 64 MB  exp(alpha*S)
__device__ float  g_O[(size_t)NHB * NT * DV];    // 64 MB

// ---------------- helpers ----------------------------------------------------
__device__ __forceinline__ uint32_t smem_u32(const void* p) {
    uint32_t a;
    asm("{ .reg .u64 t; cvta.to.shared.u64 t, %1; cvt.u32.u64 %0, t; }" : "=r"(a) : "l"(p));
    return a;
}
__device__ __forceinline__ void cp_async16(uint32_t dst, const void* src) {
    asm volatile("cp.async.cg.shared.global [%0], [%1], 16;" :: "r"(dst), "l"(src) : "memory");
}
__device__ __forceinline__ void cp_commit() { asm volatile("cp.async.commit_group;" ::: "memory"); }
template <int N> __device__ __forceinline__ void cp_wait() {
    asm volatile("cp.async.wait_group %0;" :: "n"(N) : "memory");
}
__device__ __forceinline__ void mma_f16(float* c, const uint32_t* a, const uint32_t* b) {
    asm volatile(
        "mma.sync.aligned.m16n8k16.row.col.f32.f16.f16.f32 "
        "{%0,%1,%2,%3}, {%4,%5,%6,%7}, {%8,%9}, {%0,%1,%2,%3};"
        : "+f"(c[0]), "+f"(c[1]), "+f"(c[2]), "+f"(c[3])
        : "r"(a[0]), "r"(a[1]), "r"(a[2]), "r"(a[3]), "r"(b[0]), "r"(b[1]));
}
__device__ __forceinline__ void ldmx4(uint32_t& r0, uint32_t& r1, uint32_t& r2, uint32_t& r3,
                                      uint32_t addr) {
    asm volatile("ldmatrix.sync.aligned.m8n8.x4.shared.b16 {%0,%1,%2,%3}, [%4];"
        : "=r"(r0), "=r"(r1), "=r"(r2), "=r"(r3) : "r"(addr));
}
__device__ __forceinline__ float2 h2f2(uint32_t u) {
    return __half22float2(*reinterpret_cast<__half2*>(&u));
}

// common GEMM tile geometry: 128x128 tile, 2 CTAs/SM
#define BM 128
#define BN 128
#define BKH 64                       // k halfs per stage
#define SH 72                        // smem row stride in halfs (144 B)
#define A2_TILE_BYTES (BM * SH * 2)  // 18432
#define B2_TILE_BYTES (BN * SH * 2)  // 18432
#define STAGE_BYTES (A2_TILE_BYTES + B2_TILE_BYTES)  // 36864
#define NSTG 3
#define SMEM_GEMM (NSTG * STAGE_BYTES)               // 110592

#define ISSUE_F16(it, Kd) do {                                                  \
        int _st = (it) % NSTG;                                                  \
        uint32_t _as = smem_u32(smem) + _st * STAGE_BYTES;                      \
        uint32_t _bs = _as + A2_TILE_BYTES;                                     \
        const __half* _ga = A + (size_t)bm * (Kd) + (size_t)(it) * BKH;         \
        const __half* _gb = B + (size_t)bn * (Kd) + (size_t)(it) * BKH;         \
        _Pragma("unroll")                                                       \
        for (int j = 0; j < 4; j++) {                                           \
            int idx = tid + j * 256;                                            \
            int row = idx >> 3, c8 = idx & 7;                                   \
            cp_async16(_as + (uint32_t)(row * SH * 2 + c8 * 16),                \
                       _ga + (size_t)row * (Kd) + c8 * 8);                      \
        }                                                                       \
        _Pragma("unroll")                                                       \
        for (int j = 0; j < 4; j++) {                                           \
            int idx = tid + j * 256;                                            \
            int row = idx >> 3, c8 = idx & 7;                                   \
            cp_async16(_bs + (uint32_t)(row * SH * 2 + c8 * 16),                \
                       _gb + (size_t)row * (Kd) + c8 * 8);                      \
        }                                                                       \
        cp_commit();                                                            \
    } while (0)

// per-lane ldmatrix base offsets (bytes; stride SH halfs)
#define A_LDM_OFF(base_row) ((uint32_t)(((base_row) + (lane & 15)) * (SH * 2) + (lane >> 4) * 16))
#define B_LDM_OFF(base_row) ((uint32_t)(((base_row) + ((lane & 16) >> 1) + (lane & 7)) * (SH * 2) + ((lane >> 3) & 1) * 16))

// ldmatrix offset macros for qkv_tc (stride QSH halfs)
#define QSH 72
#define A_LDM_OFF_Q(base_row) ((uint32_t)(((base_row) + (lane & 15)) * (QSH * 2) + (lane >> 4) * 16))
#define B_LDM_OFF_Q(base_row) ((uint32_t)(((base_row) + ((lane & 16) >> 1) + (lane & 7)) * (QSH * 2) + ((lane >> 3) & 1) * 16))

// ================= GEMM 1 (fp16): E = fp16(exp(alpha * Q K^T)) ===============
__global__ __launch_bounds__(256, 2) void gemm_qk_exp(
    const __half* __restrict__ A, const __half* __restrict__ B, __half* __restrict__ C,
    float alpha, size_t sA, size_t sB, size_t sC)
{
    extern __shared__ char smem[];
    const int tid = threadIdx.x;
    const int wid = tid >> 5;
    const int lane = tid & 31;
    const int g = lane >> 2;
    const int tc = lane & 3;

    A += (size_t)blockIdx.z * sA;
    B += (size_t)blockIdx.z * sB;
    C += (size_t)blockIdx.z * sC;
    const int bm = blockIdx.y * BM;
    const int bn = blockIdx.x * BN;
    const int wm = (wid & 1) * 64;
    const int wn = (wid >> 1) * 32;

    uint32_t aOff[4], bOff[2];
#pragma unroll
    for (int mt = 0; mt < 4; mt++) aOff[mt] = A_LDM_OFF(wm + mt * 16);
#pragma unroll
    for (int q = 0; q < 2; q++) bOff[q] = B_LDM_OFF(wn + q * 16) + A2_TILE_BYTES;

    float acc[4][4][4];
#pragma unroll
    for (int mt = 0; mt < 4; mt++)
#pragma unroll
        for (int nt = 0; nt < 4; nt++)
#pragma unroll
            for (int i = 0; i < 4; i++) acc[mt][nt][i] = 0.f;

    const int nk = DQK / BKH;   // 4

    ISSUE_F16(0, DQK);
    ISSUE_F16(1, DQK);

    for (int it = 0; it < nk; it++) {
        if (it < nk - 1) cp_wait<1>(); else cp_wait<0>();
        __syncthreads();
        if (it + 2 < nk) ISSUE_F16(it + 2, DQK);

        uint32_t stg = smem_u32(smem) + (it % NSTG) * STAGE_BYTES;

#pragma unroll
        for (int ks = 0; ks < 4; ks++) {
            uint32_t koff = stg + ks * 32;
            uint32_t a[4][4], b[4][2];
#pragma unroll
            for (int mt = 0; mt < 4; mt++)
                ldmx4(a[mt][0], a[mt][1], a[mt][2], a[mt][3], koff + aOff[mt]);
#pragma unroll
            for (int q = 0; q < 2; q++)
                ldmx4(b[2 * q][0], b[2 * q][1], b[2 * q + 1][0], b[2 * q + 1][1],
                      koff + bOff[q]);
#pragma unroll
            for (int mt = 0; mt < 4; mt++)
#pragma unroll
                for (int nt = 0; nt < 4; nt++)
                    mma_f16(acc[mt][nt], a[mt], b[nt]);
        }
    }

    // epilogue: E = fp16(exp(alpha * S))
#pragma unroll
    for (int mt = 0; mt < 4; mt++) {
#pragma unroll
        for (int nt = 0; nt < 4; nt++) {
            int row = bm + wm + mt * 16 + g;
            int col = bn + wn + nt * 8 + 2 * tc;
            __half2 e0 = __float22half2_rn(
                make_float2(__expf(acc[mt][nt][0] * alpha), __expf(acc[mt][nt][1] * alpha)));
            __half2 e1 = __float22half2_rn(
                make_float2(__expf(acc[mt][nt][2] * alpha), __expf(acc[mt][nt][3] * alpha)));
            *(uint32_t*)&C[(size_t)row * NT + col]       = *(uint32_t*)&e0;
            *(uint32_t*)&C[(size_t)(row + 8) * NT + col] = *(uint32_t*)&e1;
        }
    }
}

// ================= GEMM 2 (fp16): O = (E V) / rowsum(E) ======================
__global__ __launch_bounds__(256, 2) void gemm_pv_norm(
    const __half* __restrict__ A, const __half* __restrict__ B,
    float* __restrict__ C, size_t sA, size_t sB, size_t sC)
{
    extern __shared__ char smem[];
    __shared__ float rowinv[BM];
    const int tid = threadIdx.x;
    const int wid = tid >> 5;
    const int lane = tid & 31;
    const int g = lane >> 2;
    const int tc = lane & 3;

    A += (size_t)blockIdx.z * sA;
    B += (size_t)blockIdx.z * sB;
    C += (size_t)blockIdx.z * sC;
    const int bm = blockIdx.y * BM;
    const int bn = blockIdx.x * BN;
    const int wm = (wid & 1) * 64;
    const int wn = (wid >> 1) * 32;

    uint32_t aOff[4], bOff[2];
#pragma unroll
    for (int mt = 0; mt < 4; mt++) aOff[mt] = A_LDM_OFF(wm + mt * 16);
#pragma unroll
    for (int q = 0; q < 2; q++) bOff[q] = B_LDM_OFF(wn + q * 16) + A2_TILE_BYTES;

    float acc[4][4][4];
#pragma unroll
    for (int mt = 0; mt < 4; mt++)
#pragma unroll
        for (int nt = 0; nt < 4; nt++)
#pragma unroll
            for (int i = 0; i < 4; i++) acc[mt][nt][i] = 0.f;

    float rs[4][2];
#pragma unroll
    for (int mt = 0; mt < 4; mt++) { rs[mt][0] = 0.f; rs[mt][1] = 0.f; }

    const int nk = NT / BKH;   // 32

    ISSUE_F16(0, NT);
    ISSUE_F16(1, NT);

    for (int it = 0; it < nk; it++) {
        if (it < nk - 1) cp_wait<1>(); else cp_wait<0>();
        __syncthreads();
        if (it + 2 < nk) ISSUE_F16(it + 2, NT);

        uint32_t stg = smem_u32(smem) + (it % NSTG) * STAGE_BYTES;

#pragma unroll
        for (int ks = 0; ks < 4; ks++) {
            uint32_t koff = stg + ks * 32;
            uint32_t a[4][4], b[4][2];
#pragma unroll
            for (int mt = 0; mt < 4; mt++)
                ldmx4(a[mt][0], a[mt][1], a[mt][2], a[mt][3], koff + aOff[mt]);
            if (wid < 2) {   // wn==0 warps: exact row sums of E
#pragma unroll
                for (int mt = 0; mt < 4; mt++) {
                    float2 f0 = h2f2(a[mt][0]), f2 = h2f2(a[mt][2]);
                    float2 f1 = h2f2(a[mt][1]), f3 = h2f2(a[mt][3]);
                    rs[mt][0] += (f0.x + f0.y) + (f2.x + f2.y);
                    rs[mt][1] += (f1.x + f1.y) + (f3.x + f3.y);
                }
            }
#pragma unroll
            for (int q = 0; q < 2; q++)
                ldmx4(b[2 * q][0], b[2 * q][1], b[2 * q + 1][0], b[2 * q + 1][1],
                      koff + bOff[q]);
#pragma unroll
            for (int mt = 0; mt < 4; mt++)
#pragma unroll
                for (int nt = 0; nt < 4; nt++)
                    mma_f16(acc[mt][nt], a[mt], b[nt]);
        }
    }

    if (wid < 2) {
#pragma unroll
        for (int mt = 0; mt < 4; mt++) {
#pragma unroll
            for (int h2 = 0; h2 < 2; h2++) {
                float s = rs[mt][h2];
                s += __shfl_xor_sync(0xffffffffu, s, 1);
                s += __shfl_xor_sync(0xffffffffu, s, 2);
                if (tc == 0) rowinv[wm + mt * 16 + g + h2 * 8] = 1.f / s;
            }
        }
    }
    __syncthreads();

#pragma unroll
    for (int mt = 0; mt < 4; mt++) {
        float inv0 = rowinv[wm + mt * 16 + g];
        float inv1 = rowinv[wm + mt * 16 + g + 8];
#pragma unroll
        for (int nt = 0; nt < 4; nt++) {
            int row = bm + wm + mt * 16 + g;
            int col = bn + wn + nt * 8 + 2 * tc;
            float2 v0 = make_float2(acc[mt][nt][0] * inv0, acc[mt][nt][1] * inv0);
            float2 v1 = make_float2(acc[mt][nt][2] * inv1, acc[mt][nt][3] * inv1);
            *(float2*)&C[(size_t)row * DV + col] = v0;
            *(float2*)&C[(size_t)(row + 8) * DV + col] = v1;
        }
    }
}

// ---------------- kernel 1: tensor-core QKV projection + PReLU + LN ----------
#define SM_W 0
#define SM_X 13824
#define SM_OUT 50688
#define SMEM_QKV (SM_OUT + 128 * 97 * 4)    // 100352 B

__global__ __launch_bounds__(256, 1) void qkv_tc(
    const float* __restrict__ x,
    const float* __restrict__ Wq, const float* __restrict__ bq, const float* __restrict__ aq,
    const float* __restrict__ gq, const float* __restrict__ betaq,
    const float* __restrict__ Wk, const float* __restrict__ bk, const float* __restrict__ ak,
    const float* __restrict__ gk, const float* __restrict__ betak,
    const float* __restrict__ Wv, const float* __restrict__ bv, const float* __restrict__ av,
    const float* __restrict__ gv, const float* __restrict__ betav)
{
    extern __shared__ char smem[];
    __half* sW = (__half*)(smem + SM_W);
    __half* sX = (__half*)(smem + SM_X);
    float* sOut = (float*)(smem + SM_OUT);

    const int tid = threadIdx.x;
    const int wid = tid >> 5;
    const int lane = tid & 31;
    const int g = lane >> 2;
    const int tc = lane & 3;
    const int b = blockIdx.y;
    const int nbase = blockIdx.x * 256;

    for (int i = tid; i < 96 * 64; i += 256) {
        int row = i >> 6, c = i & 63;
        float w;
        if (row < 16)      w = Wq[row * NC + c];
        else if (row < 32) w = Wk[(row - 16) * NC + c];
        else               w = Wv[(row - 32) * NC + c];
        sW[row * QSH + c] = __float2half_rn(w);
    }
    {
        const float* xpf = x + (size_t)b * NC * NTF + nbase;
        for (int i = tid; i < 64 * 128; i += 256) {
            int r = i >> 7;
            int u = i & 127;
            float2 v = *(const float2*)(xpf + (size_t)r * NTF + 2 * u);
            sX[(2 * u) * QSH + r]     = __float2half_rn(v.x);
            sX[(2 * u + 1) * QSH + r] = __float2half_rn(v.y);
        }
    }
    __syncthreads();

    const int wm = (wid & 1) * 48;
    const int wn = (wid >> 1) * 64;
    uint32_t sWb = smem_u32(sW);
    uint32_t sXb = smem_u32(sX);

    uint32_t a[3][4][4];
#pragma unroll
    for (int mt = 0; mt < 3; mt++) {
        uint32_t off = sWb + A_LDM_OFF_Q(wm + mt * 16);
#pragma unroll
        for (int ks = 0; ks < 4; ks++)
            ldmx4(a[mt][ks][0], a[mt][ks][1], a[mt][ks][2], a[mt][ks][3], off + ks * 32);
    }

    float acc[3][8][4];
#pragma unroll
    for (int mt = 0; mt < 3; mt++)
#pragma unroll
        for (int nt = 0; nt < 8; nt++)
#pragma unroll
            for (int i = 0; i < 4; i++) acc[mt][nt][i] = 0.f;

#pragma unroll
    for (int ks = 0; ks < 4; ks++) {
        uint32_t b2[8][2];
#pragma unroll
        for (int q = 0; q < 4; q++) {
            uint32_t off = sXb + B_LDM_OFF_Q(wn + q * 16) + ks * 32;
            ldmx4(b2[2 * q][0], b2[2 * q][1], b2[2 * q + 1][0], b2[2 * q + 1][1], off);
        }
#pragma unroll
        for (int mt = 0; mt < 3; mt++)
#pragma unroll
            for (int nt = 0; nt < 8; nt++)
                mma_f16(acc[mt][nt], a[mt][ks], b2[nt]);
    }

#pragma unroll 1
    for (int bt = 0; bt < 2; bt++) {
        __syncthreads();
        if ((wid >> 2) == bt) {
#pragma unroll
            for (int mt = 0; mt < 3; mt++)
#pragma unroll
                for (int nt = 0; nt < 8; nt++)
#pragma unroll
                    for (int i = 0; i < 4; i++) {
                        int row = wm + mt * 16 + g + 8 * (i >> 1);
                        int col = (wn - bt * 128) + nt * 8 + 2 * tc + (i & 1);
                        sOut[col * 97 + row] = acc[mt][nt][i];
                    }
        }
        __syncthreads();
        {
            const int c = tid & 127;
            const int hh = tid >> 7;
            const int n = nbase + bt * 128 + c;
            const int t = n >> 6;
            const int f = n & 63;
            const float* so = sOut + c * 97;

#pragma unroll
            for (int h2 = 0; h2 < 2; h2++) {
                const int h = hh * 2 + h2;
                {
                    float y[4]; float aph = aq[h]; float mu = 0.f;
#pragma unroll
                    for (int j = 0; j < 4; j++) {
                        float v = so[4 * h + j] + bq[4 * h + j];
                        v = (v >= 0.f) ? v : aph * v;
                        y[j] = v; mu += v;
                    }
                    mu *= 0.25f;
                    float var = 0.f;
#pragma unroll
                    for (int j = 0; j < 4; j++) { float d = y[j] - mu; var += d * d; }
                    float r = rsqrtf(var * 0.25f + EPSV);
#pragma unroll
                    for (int j = 0; j < 4; j++) {
                        float o = (y[j] - mu) * r * gq[4 * h + j] + betaq[4 * h + j];
                        g_Q[((size_t)(h * NB + b) * NT + t) * DQK + j * NF + f] = __float2half_rn(o);
                    }
                }
                {
                    float y[4]; float aph = ak[h]; float mu = 0.f;
#pragma unroll
                    for (int j = 0; j < 4; j++) {
                        float v = so[16 + 4 * h + j] + bk[4 * h + j];
                        v = (v >= 0.f) ? v : aph * v;
                        y[j] = v; mu += v;
                    }
                    mu *= 0.25f;
                    float var = 0.f;
#pragma unroll
                    for (int j = 0; j < 4; j++) { float d = y[j] - mu; var += d * d; }
                    float r = rsqrtf(var * 0.25f + EPSV);
#pragma unroll
                    for (int j = 0; j < 4; j++) {
                        float o = (y[j] - mu) * r * gk[4 * h + j] + betak[4 * h + j];
                        g_K[((size_t)(h * NB + b) * NT + t) * DQK + j * NF + f] = __float2half_rn(o);
                    }
                }
                {
                    float y[16]; float aph = av[h]; float mu = 0.f;
#pragma unroll
                    for (int j = 0; j < 16; j++) {
                        float v = so[32 + 16 * h + j] + bv[16 * h + j];
                        v = (v >= 0.f) ? v : aph * v;
                        y[j] = v; mu += v;
                    }
                    mu *= (1.f / 16.f);
                    float var = 0.f;
#pragma unroll
                    for (int j = 0; j < 16; j++) { float d = y[j] - mu; var += d * d; }
                    float r = rsqrtf(var * (1.f / 16.f) + EPSV);
#pragma unroll
                    for (int j = 0; j < 16; j++) {
                        float o = (y[j] - mu) * r * gv[16 * h + j] + betav[16 * h + j];
                        g_V[((size_t)(h * NB + b) * NT + t) * DV + j * NF + f] = __float2half_rn(o);
                    }
                }
            }
        }
    }
}

// ---------------- transpose V (fp16): [t][dv] -> [dv][t] per z ----------------
__global__ __launch_bounds__(256) void transpose_v()
{
    __shared__ __half tile[32][33];
    int bt = blockIdx.x * 32, bd = blockIdx.y * 32;
    size_t base = (size_t)blockIdx.z * NT * DV;
    int tx = threadIdx.x, ty = threadIdx.y;
#pragma unroll
    for (int j = 0; j < 4; j++)
        tile[ty + j * 8][tx] = g_V[base + (size_t)(bt + ty + j * 8) * DV + bd + tx];
    __syncthreads();
#pragma unroll
    for (int j = 0; j < 4; j++)
        g_Vt[base + (size_t)(bd + ty + j * 8) * NT + bt + tx] = tile[tx][ty + j * 8];
}

// ---------------- out_kernel v4: projection + PReLU + LN + residual ----------
// block = 256 threads handles TWO t positions (both b in grid.y).
#define OK_SWT 0
#define OK_SOG 17408
#define OK_RED (OK_SOG + 2 * 17408)
#define SMEM_OUTK (OK_RED + 4096)         // 56320

__global__ __launch_bounds__(256, 2) void out_kernel(
    const float* __restrict__ x,
    const float* __restrict__ Wp, const float* __restrict__ bp, const float* __restrict__ ap,
    const float* __restrict__ gp, const float* __restrict__ betap,
    float* __restrict__ out)
{
    extern __shared__ char smem[];
    float* sWt = (float*)(smem + OK_SWT);
    float* sOg = (float*)(smem + OK_SOG);
    float* sred = (float*)(smem + OK_RED);

    const int tid = threadIdx.x;
    const int t0 = blockIdx.x * 2;
    const int b = blockIdx.y;

    for (int i = tid; i < NC * NC; i += 256) {
        int o = i >> 6, c = i & 63;
        sWt[c * 68 + o] = Wp[i];
    }
#pragma unroll
    for (int tt = 0; tt < 2; tt++) {
#pragma unroll
        for (int h = 0; h < NH; h++) {
            const float4* src = (const float4*)&g_O[((size_t)(h * NB + b) * NT + t0 + tt) * DV];
            float4 val = src[tid];
            int vc = tid >> 4;
            int f0 = (tid & 15) * 4;
            *(float4*)&sOg[tt * (NC * 68) + (h * 16 + vc) * 68 + f0] = val;
        }
    }
    __syncthreads();

    const int j = tid >> 6;
    const int f = tid & 63;
    const int o0 = 16 * j;

    float acc0[16], acc1[16];
#pragma unroll
    for (int i = 0; i < 16; i++) { acc0[i] = 0.f; acc1[i] = 0.f; }

#pragma unroll 4
    for (int c = 0; c < NC; c++) {
        float oga = sOg[c * 68 + f];
        float ogb = sOg[NC * 68 + c * 68 + f];
        float4 w0 = *(const float4*)&sWt[c * 68 + o0];
        float4 w1 = *(const float4*)&sWt[c * 68 + o0 + 4];
        float4 w2 = *(const float4*)&sWt[c * 68 + o0 + 8];
        float4 w3 = *(const float4*)&sWt[c * 68 + o0 + 12];
        acc0[0] += w0.x * oga;  acc0[1] += w0.y * oga;  acc0[2] += w0.z * oga;  acc0[3] += w0.w * oga;
        acc0[4] += w1.x * oga;  acc0[5] += w1.y * oga;  acc0[6] += w1.z * oga;  acc0[7] += w1.w * oga;
        acc0[8] += w2.x * oga;  acc0[9] += w2.y * oga;  acc0[10] += w2.z * oga; acc0[11] += w2.w * oga;
        acc0[12] += w3.x * oga; acc0[13] += w3.y * oga; acc0[14] += w3.z * oga; acc0[15] += w3.w * oga;
        acc1[0] += w0.x * ogb;  acc1[1] += w0.y * ogb;  acc1[2] += w0.z * ogb;  acc1[3] += w0.w * ogb;
        acc1[4] += w1.x * ogb;  acc1[5] += w1.y * ogb;  acc1[6] += w1.z * ogb;  acc1[7] += w1.w * ogb;
        acc1[8] += w2.x * ogb;  acc1[9] += w2.y * ogb;  acc1[10] += w2.z * ogb; acc1[11] += w2.w * ogb;
        acc1[12] += w3.x * ogb; acc1[13] += w3.y * ogb; acc1[14] += w3.z * ogb; acc1[15] += w3.w * ogb;
    }

    float a = ap[0];
    {
        float s1 = 0.f, s2 = 0.f, u1 = 0.f, u2 = 0.f;
#pragma unroll
        for (int i = 0; i < 16; i++) {
            float y = acc0[i] + bp[o0 + i];
            y = (y >= 0.f) ? y : a * y;
            acc0[i] = y; s1 += y; s2 += y * y;
            float z = acc1[i] + bp[o0 + i];
            z = (z >= 0.f) ? z : a * z;
            acc1[i] = z; u1 += z; u2 += z * z;
        }
        sred[((0 * 2 + 0) * 4 + j) * 64 + f] = s1;
        sred[((1 * 2 + 0) * 4 + j) * 64 + f] = s2;
        sred[((0 * 2 + 1) * 4 + j) * 64 + f] = u1;
        sred[((1 * 2 + 1) * 4 + j) * 64 + f] = u2;
    }
    __syncthreads();

#pragma unroll
    for (int tt = 0; tt < 2; tt++) {
        float* base1 = sred + (0 * 2 + tt) * 4 * 64;
        float* base2 = sred + (1 * 2 + tt) * 4 * 64;
        float s1 = base1[0 * 64 + f] + base1[1 * 64 + f] + base1[2 * 64 + f] + base1[3 * 64 + f];
        float s2 = base2[0 * 64 + f] + base2[1 * 64 + f] + base2[2 * 64 + f] + base2[3 * 64 + f];
        float mu = s1 * (1.f / NC);
        float var = s2 * (1.f / NC) - mu * mu;
        float r = rsqrtf(var + EPSV);
        float* acc = tt ? acc1 : acc0;
#pragma unroll
        for (int i = 0; i < 16; i++) {
            int o = o0 + i;
            size_t idx = (((size_t)b * NC + o) * NT + t0 + tt) * NF + f;
            out[idx] = (acc[i] - mu) * r * gp[o] + betap[o] + x[idx];
        }
    }
}

// ---------------- launch ------------------------------------------------------
extern "C" void kernel_launch(void* const* d_in, const int* in_sizes, int n_in,
                              void* d_out, int out_size)
{
    const float* x     = (const float*)d_in[0];
    const float* Wq    = (const float*)d_in[1];
    const float* bq    = (const float*)d_in[2];
    const float* aq    = (const float*)d_in[3];
    const float* gq    = (const float*)d_in[4];
    const float* betaq = (const float*)d_in[5];
    const float* Wk    = (const float*)d_in[6];
    const float* bk    = (const float*)d_in[7];
    const float* ak    = (const float*)d_in[8];
    const float* gk    = (const float*)d_in[9];
    const float* betak = (const float*)d_in[10];
    const float* Wv    = (const float*)d_in[11];
    const float* bv    = (const float*)d_in[12];
    const float* av    = (const float*)d_in[13];
    const float* gv    = (const float*)d_in[14];
    const float* betav = (const float*)d_in[15];
    const float* Wp    = (const float*)d_in[16];
    const float* bp    = (const float*)d_in[17];
    const float* ap    = (const float*)d_in[18];
    const float* gp    = (const float*)d_in[19];
    const float* betap = (const float*)d_in[20];
    float* out = (float*)d_out;

    float* pO;
    __half *pQ, *pK, *pV, *pVt, *pE;
    cudaGetSymbolAddress((void**)&pQ, g_Q);
    cudaGetSymbolAddress((void**)&pK, g_K);
    cudaGetSymbolAddress((void**)&pV, g_V);
    cudaGetSymbolAddress((void**)&pVt, g_Vt);
    cudaGetSymbolAddress((void**)&pE, g_E);
    cudaGetSymbolAddress((void**)&pO, g_O);

    cudaFuncSetAttribute(gemm_qk_exp, cudaFuncAttributeMaxDynamicSharedMemorySize, SMEM_GEMM);
    cudaFuncSetAttribute(gemm_pv_norm, cudaFuncAttributeMaxDynamicSharedMemorySize, SMEM_GEMM);
    cudaFuncSetAttribute(qkv_tc, cudaFuncAttributeMaxDynamicSharedMemorySize, SMEM_QKV);
    cudaFuncSetAttribute(out_kernel, cudaFuncAttributeMaxDynamicSharedMemorySize, SMEM_OUTK);

    // streams/events created once on the (uncaptured) correctness call
    static cudaStream_t s1 = nullptr;
    static cudaEvent_t evQKV, evT;
    if (s1 == nullptr) {
        cudaStreamCreateWithFlags(&s1, cudaStreamNonBlocking);
        cudaEventCreateWithFlags(&evQKV, cudaEventDisableTiming);
        cudaEventCreateWithFlags(&evT, cudaEventDisableTiming);
    }

    // 1) QKV projection (stream 0)
    qkv_tc<<<dim3(NTF / 256, NB), 256, SMEM_QKV>>>(
        x, Wq, bq, aq, gq, betaq, Wk, bk, ak, gk, betak, Wv, bv, av, gv, betav);
    cudaEventRecord(evQKV, 0);

    // 2) V transpose on s1 — overlaps gemm_qk on stream 0
    cudaStreamWaitEvent(s1, evQKV, 0);
    transpose_v<<<dim3(NT / 32, DV / 32, NHB), dim3(32, 8), 0, s1>>>();
    cudaEventRecord(evT, s1);

    // 3) E = fp16(exp((1/16) Q K^T))  (stream 0, concurrent with transpose)
    gemm_qk_exp<<<dim3(NT / BN, NT / BM, NHB), 256, SMEM_GEMM>>>(
        pQ, pK, pE, 0.0625f,
        (size_t)NT * DQK, (size_t)NT * DQK, (size_t)NT * NT);

    // 4) O = (E V) / rowsum(E)  (full grid; after transpose joins)
    cudaStreamWaitEvent(0, evT, 0);
    gemm_pv_norm<<<dim3(DV / BN, NT / BM, NHB), 256, SMEM_GEMM>>>(
        pE, pVt, pO,
        (size_t)NT * NT, (size_t)DV * NT, (size_t)NT * DV);

    // 5) output projection (2 t per block) + PReLU + LN + residual
    out_kernel<<<dim3(NT / 2, NB), 256, SMEM_OUTK>>>(
        x, Wp, bp, ap, gp, betap, out);
}